// round 12
// baseline (speedup 1.0000x reference)
#include <cuda_runtime.h>
#include <math.h>

// Problem shape (fixed by reference setup_inputs)
#define BATCH  2
#define DDIM   1024
#define NST    16
#define LEN    2048
#define ROWS   (BATCH * DDIM)     // 2048
#define CHUNKS 64
#define CLEN   (LEN / CHUNKS)     // 32
#define SUBT   16                 // staging subtile (timesteps)
#define BPITCH 20                 // B/C smem pitch in floats (80B, 16B-aligned)
#define TPITCH 20                 // row-tile pitch (80B, 16B-aligned, conflict-free reads)
#define LOG2E    1.4426950408889634f
#define RCP_LOG2 0.6931471805599453f

// Scratch (no cudaMalloc allowed)
__device__ float g_spt  [LEN * ROWS];           // softplus(delta), transposed [t][row]
__device__ float g_ut   [LEN * ROWS];           // u, transposed [t][row]
__device__ float g_hloc [ROWS * CHUNKS * NST];  // per-chunk local final state
__device__ float g_sumsp[ROWS * CHUNKS];        // per-chunk sum of softplus
__device__ float g_carry[ROWS * CHUNKS * NST];  // carry-in state per chunk

typedef unsigned long long u64;

union F4P { float4 v; u64 p[2]; };
union U2F { u64 u; float f[2]; };

__device__ __forceinline__ u64 mul2(u64 a, u64 b) {
    u64 d;
    asm("mul.rn.f32x2 %0, %1, %2;" : "=l"(d) : "l"(a), "l"(b));
    return d;
}
__device__ __forceinline__ u64 fma2(u64 a, u64 b, u64 c) {
    u64 d;
    asm("fma.rn.f32x2 %0, %1, %2, %3;" : "=l"(d) : "l"(a), "l"(b), "l"(c));
    return d;
}
__device__ __forceinline__ u64 add2(u64 a, u64 b) {
    u64 d;
    asm("add.rn.f32x2 %0, %1, %2;" : "=l"(d) : "l"(a), "l"(b));
    return d;
}
__device__ __forceinline__ u64 splat2(float x) {
    U2F r; r.f[0] = x; r.f[1] = x; return r.u;
}

__device__ __forceinline__ float ex2f(float x) {
    float y;
    asm("ex2.approx.ftz.f32 %0, %1;" : "=f"(y) : "f"(x));
    return y;
}
__device__ __forceinline__ float lg2f(float x) {
    float y;
    asm("lg2.approx.ftz.f32 %0, %1;" : "=f"(y) : "f"(x));
    return y;
}
__device__ __forceinline__ float softplus_f(float x) {
    if (x > 20.0f) return x;
    return lg2f(1.0f + ex2f(x * LOG2E)) * RCP_LOG2;
}
__device__ __forceinline__ float silu_f(float x) {
    float e = ex2f(-x * LOG2E);
    return __fdividef(x, 1.0f + e);
}

// exp2 of both halves via MUFU (XU pipe) — proven fastest variant (round 8).
__device__ __forceinline__ u64 ex2_pair(u64 x2) {
    U2F in; in.u = x2;
    U2F out;
    out.f[0] = ex2f(in.f[0]);
    out.f[1] = ex2f(in.f[1]);
    return out.u;
}

// ------------------------------------------------------------------ phase 1
// Thread = (row, chunk), 16 states in 8 packed f32x2 registers.
// Block = 128 rows, one chunk. Grid = (ROWS/128, CHUNKS) = (16, 64).
// Writes sp AND u transposed [t][row] so phase 3 needs no u staging tile.
__global__ void __launch_bounds__(128, 6)
phase1_kernel(const float* __restrict__ u,
              const float* __restrict__ delta,
              const float* __restrict__ A,
              const float* __restrict__ B) {
    __shared__ __align__(16) float Bsm[CLEN][BPITCH];
    __shared__ __align__(16) float Dt[128][TPITCH];
    __shared__ __align__(16) float Ut[128][TPITCH];

    const int tid     = threadIdx.x;
    const int rowbase = blockIdx.x * 128;
    const int row     = rowbase + tid;
    const int chunk   = blockIdx.y;
    const int b       = row >> 10;         // DDIM = 1024
    const int d       = row & (DDIM - 1);
    const int t0      = chunk * CLEN;

    // Stage B tile [t][n] (128 slots = one float4 per thread)
    const float* __restrict__ Bb = B + (size_t)b * NST * LEN + t0;
    {
        const int i  = tid;
        const int nn = i >> 3;             // CLEN/4 = 8 slots per state
        const int t4 = (i & 7) << 2;
        float4 v = *reinterpret_cast<const float4*>(Bb + nn * LEN + t4);
        Bsm[t4 + 0][nn] = v.x; Bsm[t4 + 1][nn] = v.y;
        Bsm[t4 + 2][nn] = v.z; Bsm[t4 + 3][nn] = v.w;
    }

    u64 A2p[8];
    {
        const u64 l2 = splat2(LOG2E);
        const float4* Ap = reinterpret_cast<const float4*>(A + d * NST);
        #pragma unroll
        for (int q = 0; q < 4; q++) {
            F4P a; a.v = Ap[q];
            A2p[q*2+0] = mul2(a.p[0], l2);
            A2p[q*2+1] = mul2(a.p[1], l2);
        }
    }

    u64 h2[8];
    #pragma unroll
    for (int p = 0; p < 8; p++) h2[p] = 0ull;
    float ssum = 0.0f;

    #pragma unroll 1
    for (int sub = 0; sub < CLEN / SUBT; sub++) {
        const int tb = t0 + sub * SUBT;
        __syncthreads();   // previous tile consumed / B staged
        // Coalesced staging: 128 rows x 16 t = 512 float4 slots, 4 per thread
        #pragma unroll
        for (int s = 0; s < 4; s++) {
            const int f = s * 128 + tid;
            const int r = f >> 2;
            const int c = (f & 3) << 2;
            const size_t gofs = (size_t)(rowbase + r) * LEN + tb + c;
            *reinterpret_cast<float4*>(&Dt[r][c]) =
                *reinterpret_cast<const float4*>(delta + gofs);
            *reinterpret_cast<float4*>(&Ut[r][c]) =
                *reinterpret_cast<const float4*>(u + gofs);
        }
        __syncthreads();

        float* __restrict__ sptp = g_spt + (size_t)tb * ROWS + row;
        float* __restrict__ utp  = g_ut  + (size_t)tb * ROWS + row;

        #pragma unroll 1
        for (int tq = 0; tq < SUBT; tq += 4) {
            float4 d4 = *reinterpret_cast<const float4*>(&Dt[tid][tq]);
            float4 u4 = *reinterpret_cast<const float4*>(&Ut[tid][tq]);
            float sp[4] = {softplus_f(d4.x), softplus_f(d4.y),
                           softplus_f(d4.z), softplus_f(d4.w)};
            float uu[4] = {u4.x, u4.y, u4.z, u4.w};

            #pragma unroll
            for (int k = 0; k < 4; k++) {
                const int tt = sub * SUBT + tq + k;   // index into Bsm
                sptp[(size_t)(tq + k) * ROWS] = sp[k];
                utp [(size_t)(tq + k) * ROWS] = uu[k];
                ssum += sp[k];
                const u64 sp2  = splat2(sp[k]);
                const u64 dbu2 = splat2(sp[k] * uu[k]);

                const float4* Bt = reinterpret_cast<const float4*>(&Bsm[tt][0]);
                F4P b0, b1, b2, b3;
                b0.v = Bt[0]; b1.v = Bt[1]; b2.v = Bt[2]; b3.v = Bt[3];
                const u64 B2[8] = {b0.p[0], b0.p[1], b1.p[0], b1.p[1],
                                   b2.p[0], b2.p[1], b3.p[0], b3.p[1]};
                #pragma unroll
                for (int p = 0; p < 8; p++) {
                    const u64 a2 = ex2_pair(mul2(sp2, A2p[p]));
                    h2[p] = fma2(a2, h2[p], mul2(dbu2, B2[p]));
                }
            }
        }
    }

    float* __restrict__ hp = g_hloc + ((size_t)row * CHUNKS + chunk) * NST;
    #pragma unroll
    for (int q = 0; q < 4; q++) {
        F4P o; o.p[0] = h2[q*2+0]; o.p[1] = h2[q*2+1];
        *reinterpret_cast<float4*>(hp + q * 4) = o.v;
    }
    g_sumsp[row * CHUNKS + chunk] = ssum;
}

// ------------------------------------------------------------------ phase 2
// One thread per (row, n): sequential combine over CHUNKS.
__global__ void __launch_bounds__(256) phase2_kernel(const float* __restrict__ A) {
    const int idx = blockIdx.x * blockDim.x + threadIdx.x;   // 0..ROWS*NST-1
    const int row = idx >> 4;
    const int n   = idx & (NST - 1);
    const int d   = row & (DDIM - 1);
    const float A2 = A[d * NST + n] * LOG2E;

    float H = 0.0f;
    #pragma unroll 8
    for (int c = 0; c < CHUNKS; c++) {
        g_carry[((size_t)row * CHUNKS + c) * NST + n] = H;
        float P = ex2f(A2 * g_sumsp[row * CHUNKS + c]);
        H = fmaf(P, H, g_hloc[((size_t)row * CHUNKS + c) * NST + n]);
    }
}

// ------------------------------------------------------------------ phase 3
// Thread = (row, chunk); h from carry; sp/u read as coalesced direct LDG
// from the transposed scratch; only z (in) and y (out) go through one
// shared tile, reused in place. Smem ~15.4 KB -> many blocks/SM.
__global__ void __launch_bounds__(128, 6)
phase3_kernel(const float* __restrict__ A,
              const float* __restrict__ B,
              const float* __restrict__ C,
              const float* __restrict__ Dv,
              const float* __restrict__ z,
              float* __restrict__ y) {
    __shared__ __align__(16) float Bsm[CLEN][BPITCH];
    __shared__ __align__(16) float Csm[CLEN][BPITCH];
    __shared__ __align__(16) float Zt[128][TPITCH];   // z in, y out (reused)

    const int tid     = threadIdx.x;
    const int rowbase = blockIdx.x * 128;
    const int row     = rowbase + tid;
    const int chunk   = blockIdx.y;
    const int b       = row >> 10;
    const int d       = row & (DDIM - 1);
    const int t0      = chunk * CLEN;

    const float* __restrict__ Bb = B + (size_t)b * NST * LEN + t0;
    const float* __restrict__ Cb = C + (size_t)b * NST * LEN + t0;
    {
        const int i  = tid;
        const int nn = i >> 3;
        const int t4 = (i & 7) << 2;
        float4 v = *reinterpret_cast<const float4*>(Bb + nn * LEN + t4);
        Bsm[t4 + 0][nn] = v.x; Bsm[t4 + 1][nn] = v.y;
        Bsm[t4 + 2][nn] = v.z; Bsm[t4 + 3][nn] = v.w;
        float4 w = *reinterpret_cast<const float4*>(Cb + nn * LEN + t4);
        Csm[t4 + 0][nn] = w.x; Csm[t4 + 1][nn] = w.y;
        Csm[t4 + 2][nn] = w.z; Csm[t4 + 3][nn] = w.w;
    }

    u64 A2p[8];
    {
        const u64 l2 = splat2(LOG2E);
        const float4* Ap = reinterpret_cast<const float4*>(A + d * NST);
        #pragma unroll
        for (int q = 0; q < 4; q++) {
            F4P a; a.v = Ap[q];
            A2p[q*2+0] = mul2(a.p[0], l2);
            A2p[q*2+1] = mul2(a.p[1], l2);
        }
    }
    const float Dd = Dv[d];

    u64 h2[8];
    {
        const float4* cp = reinterpret_cast<const float4*>(
            g_carry + ((size_t)row * CHUNKS + chunk) * NST);
        #pragma unroll
        for (int q = 0; q < 4; q++) {
            F4P c4; c4.v = cp[q];
            h2[q*2+0] = c4.p[0];
            h2[q*2+1] = c4.p[1];
        }
    }

    #pragma unroll 1
    for (int sub = 0; sub < CLEN / SUBT; sub++) {
        const int tb = t0 + sub * SUBT;
        __syncthreads();   // previous writeout done / B,C staged
        #pragma unroll
        for (int s = 0; s < 4; s++) {
            const int f = s * 128 + tid;
            const int r = f >> 2;
            const int c = (f & 3) << 2;
            *reinterpret_cast<float4*>(&Zt[r][c]) =
                *reinterpret_cast<const float4*>(
                    z + (size_t)(rowbase + r) * LEN + tb + c);
        }
        __syncthreads();

        const float* __restrict__ sptp = g_spt + (size_t)tb * ROWS + row;
        const float* __restrict__ utp  = g_ut  + (size_t)tb * ROWS + row;

        #pragma unroll 1
        for (int tq = 0; tq < SUBT; tq += 4) {
            float4 z4 = *reinterpret_cast<const float4*>(&Zt[tid][tq]);
            float zz[4] = {z4.x, z4.y, z4.z, z4.w};
            float sp[4], uu[4];
            #pragma unroll
            for (int k = 0; k < 4; k++) {
                sp[k] = sptp[(size_t)(tq + k) * ROWS];
                uu[k] = utp [(size_t)(tq + k) * ROWS];
            }
            float r4[4];

            #pragma unroll
            for (int k = 0; k < 4; k++) {
                const int tt    = sub * SUBT + tq + k;
                const float spv = sp[k];
                const float uv  = uu[k];
                const u64 sp2   = splat2(spv);
                const u64 dbu2  = splat2(spv * uv);

                const float4* Bt = reinterpret_cast<const float4*>(&Bsm[tt][0]);
                const float4* Ct = reinterpret_cast<const float4*>(&Csm[tt][0]);
                F4P b0, b1, b2, b3, c0, c1, c2, c3;
                b0.v = Bt[0]; b1.v = Bt[1]; b2.v = Bt[2]; b3.v = Bt[3];
                c0.v = Ct[0]; c1.v = Ct[1]; c2.v = Ct[2]; c3.v = Ct[3];
                const u64 B2[8] = {b0.p[0], b0.p[1], b1.p[0], b1.p[1],
                                   b2.p[0], b2.p[1], b3.p[0], b3.p[1]};
                const u64 C2[8] = {c0.p[0], c0.p[1], c1.p[0], c1.p[1],
                                   c2.p[0], c2.p[1], c3.p[0], c3.p[1]};

                u64 accA = 0ull, accB = 0ull;
                #pragma unroll
                for (int p = 0; p < 8; p += 2) {
                    const u64 a2_0 = ex2_pair(mul2(sp2, A2p[p]));
                    h2[p] = fma2(a2_0, h2[p], mul2(dbu2, B2[p]));
                    accA = fma2(C2[p], h2[p], accA);
                    const u64 a2_1 = ex2_pair(mul2(sp2, A2p[p+1]));
                    h2[p+1] = fma2(a2_1, h2[p+1], mul2(dbu2, B2[p+1]));
                    accB = fma2(C2[p+1], h2[p+1], accB);
                }
                U2F acc; acc.u = add2(accA, accB);
                const float sres = (acc.f[0] + acc.f[1]) + uv * Dd;
                r4[k] = sres * silu_f(zz[k]);
            }

            // overwrite own row's z slots with y (same owner thread)
            *reinterpret_cast<float4*>(&Zt[tid][tq]) =
                make_float4(r4[0], r4[1], r4[2], r4[3]);
        }

        __syncthreads();   // y tile complete
        #pragma unroll
        for (int s = 0; s < 4; s++) {
            const int f = s * 128 + tid;
            const int r = f >> 2;
            const int c = (f & 3) << 2;
            *reinterpret_cast<float4*>(
                y + (size_t)(rowbase + r) * LEN + tb + c) =
                *reinterpret_cast<const float4*>(&Zt[r][c]);
        }
    }
}

extern "C" void kernel_launch(void* const* d_in, const int* in_sizes, int n_in,
                              void* d_out, int out_size) {
    // metadata order: u, delta, A, B, C, D, z, delta_softplus
    const float* u     = (const float*)d_in[0];
    const float* delta = (const float*)d_in[1];
    const float* A     = (const float*)d_in[2];
    const float* B     = (const float*)d_in[3];
    const float* C     = (const float*)d_in[4];
    const float* D     = (const float*)d_in[5];
    const float* z     = (const float*)d_in[6];
    float* y = (float*)d_out;

    dim3 grid1(ROWS / 128, CHUNKS);
    phase1_kernel<<<grid1, 128>>>(u, delta, A, B);
    phase2_kernel<<<(ROWS * NST) / 256, 256>>>(A);
    phase3_kernel<<<grid1, 128>>>(A, B, C, D, z, y);
}

// round 13
// speedup vs baseline: 1.2497x; 1.2497x over previous
#include <cuda_runtime.h>
#include <math.h>

// Problem shape (fixed by reference setup_inputs)
#define BATCH  2
#define DDIM   1024
#define NST    16
#define LEN    2048
#define ROWS   (BATCH * DDIM)     // 2048
#define CHUNKS 32
#define CLEN   (LEN / CHUNKS)     // 64
#define SUBT   32                 // staging subtile (timesteps) = 128B rows
#define BPITCH 20                 // B/C smem pitch in floats (80B, 16B-aligned)
#define TPITCH 36                 // row-tile pitch in floats (144B, 16B-aligned)
#define LOG2E    1.4426950408889634f
#define RCP_LOG2 0.6931471805599453f

// Scratch (no cudaMalloc allowed)
__device__ float g_spt  [LEN * ROWS];           // softplus(delta), transposed [t][row]
__device__ float g_ut   [LEN * ROWS];           // u, transposed [t][row]
__device__ float g_hloc [ROWS * CHUNKS * NST];  // per-chunk local final state
__device__ float g_sumsp[ROWS * CHUNKS];        // per-chunk sum of softplus
__device__ float g_carry[ROWS * CHUNKS * NST];  // carry-in state per chunk

typedef unsigned long long u64;

union F4P { float4 v; u64 p[2]; };
union U2F { u64 u; float f[2]; };

__device__ __forceinline__ u64 mul2(u64 a, u64 b) {
    u64 d;
    asm("mul.rn.f32x2 %0, %1, %2;" : "=l"(d) : "l"(a), "l"(b));
    return d;
}
__device__ __forceinline__ u64 fma2(u64 a, u64 b, u64 c) {
    u64 d;
    asm("fma.rn.f32x2 %0, %1, %2, %3;" : "=l"(d) : "l"(a), "l"(b), "l"(c));
    return d;
}
__device__ __forceinline__ u64 add2(u64 a, u64 b) {
    u64 d;
    asm("add.rn.f32x2 %0, %1, %2;" : "=l"(d) : "l"(a), "l"(b));
    return d;
}
__device__ __forceinline__ u64 splat2(float x) {
    U2F r; r.f[0] = x; r.f[1] = x; return r.u;
}

__device__ __forceinline__ float ex2f(float x) {
    float y;
    asm("ex2.approx.ftz.f32 %0, %1;" : "=f"(y) : "f"(x));
    return y;
}
__device__ __forceinline__ float lg2f(float x) {
    float y;
    asm("lg2.approx.ftz.f32 %0, %1;" : "=f"(y) : "f"(x));
    return y;
}
__device__ __forceinline__ float softplus_f(float x) {
    if (x > 20.0f) return x;
    return lg2f(1.0f + ex2f(x * LOG2E)) * RCP_LOG2;
}
// silu via tanh.approx: 1 MUFU instead of ex2 + rcp.
__device__ __forceinline__ float silu_t(float z) {
    float t;
    asm("tanh.approx.f32 %0, %1;" : "=f"(t) : "f"(z * 0.5f));
    return z * fmaf(t, 0.5f, 0.5f);
}

// exp2 of both halves via MUFU (XU pipe) — proven fastest variant (round 8).
__device__ __forceinline__ u64 ex2_pair(u64 x2) {
    U2F in; in.u = x2;
    U2F out;
    out.f[0] = ex2f(in.f[0]);
    out.f[1] = ex2f(in.f[1]);
    return out.u;
}

// ------------------------------------------------------------------ phase 1
// Thread = (row, chunk), 16 states in 8 packed f32x2 registers.
// Block = 128 rows, one chunk. Grid = (ROWS/128, CHUNKS) = (16, 32).
// Writes sp AND u transposed [t][row] so phase 3 needs neither tile.
__global__ void __launch_bounds__(128) phase1_kernel(const float* __restrict__ u,
                                                     const float* __restrict__ delta,
                                                     const float* __restrict__ A,
                                                     const float* __restrict__ B) {
    __shared__ __align__(16) float Bsm[CLEN][BPITCH];
    __shared__ __align__(16) float Dt[128][TPITCH];
    __shared__ __align__(16) float Ut[128][TPITCH];

    const int tid     = threadIdx.x;
    const int rowbase = blockIdx.x * 128;
    const int row     = rowbase + tid;
    const int chunk   = blockIdx.y;
    const int b       = row >> 10;         // DDIM = 1024
    const int d       = row & (DDIM - 1);
    const int t0      = chunk * CLEN;

    // Stage B tile [t][n]
    const float* __restrict__ Bb = B + (size_t)b * NST * LEN + t0;
    #pragma unroll
    for (int i = tid; i < NST * (CLEN / 4); i += 128) {
        const int nn = i >> 4;             // CLEN/4 = 16 slots per state
        const int t4 = (i & 15) << 2;
        float4 v = *reinterpret_cast<const float4*>(Bb + nn * LEN + t4);
        Bsm[t4 + 0][nn] = v.x; Bsm[t4 + 1][nn] = v.y;
        Bsm[t4 + 2][nn] = v.z; Bsm[t4 + 3][nn] = v.w;
    }

    u64 A2p[8];
    {
        const u64 l2 = splat2(LOG2E);
        const float4* Ap = reinterpret_cast<const float4*>(A + d * NST);
        #pragma unroll
        for (int q = 0; q < 4; q++) {
            F4P a; a.v = Ap[q];
            A2p[q*2+0] = mul2(a.p[0], l2);
            A2p[q*2+1] = mul2(a.p[1], l2);
        }
    }

    u64 h2[8];
    #pragma unroll
    for (int p = 0; p < 8; p++) h2[p] = 0ull;
    float ssum = 0.0f;

    #pragma unroll 1
    for (int sub = 0; sub < CLEN / SUBT; sub++) {
        const int tb = t0 + sub * SUBT;
        __syncthreads();   // previous tile consumed / B staged
        #pragma unroll
        for (int s = 0; s < 8; s++) {
            const int f = s * 128 + tid;
            const int r = f >> 3;
            const int c = (f & 7) << 2;
            const size_t gofs = (size_t)(rowbase + r) * LEN + tb + c;
            *reinterpret_cast<float4*>(&Dt[r][c]) =
                *reinterpret_cast<const float4*>(delta + gofs);
            *reinterpret_cast<float4*>(&Ut[r][c]) =
                *reinterpret_cast<const float4*>(u + gofs);
        }
        __syncthreads();

        float* __restrict__ sptp = g_spt + (size_t)tb * ROWS + row;
        float* __restrict__ utp  = g_ut  + (size_t)tb * ROWS + row;

        #pragma unroll 1
        for (int tq = 0; tq < SUBT; tq += 4) {
            float4 d4 = *reinterpret_cast<const float4*>(&Dt[tid][tq]);
            float4 u4 = *reinterpret_cast<const float4*>(&Ut[tid][tq]);
            float sp[4] = {softplus_f(d4.x), softplus_f(d4.y),
                           softplus_f(d4.z), softplus_f(d4.w)};
            float uu[4] = {u4.x, u4.y, u4.z, u4.w};

            #pragma unroll
            for (int k = 0; k < 4; k++) {
                const int tt = sub * SUBT + tq + k;   // index into Bsm
                sptp[(size_t)(tq + k) * ROWS] = sp[k];
                utp [(size_t)(tq + k) * ROWS] = uu[k];
                ssum += sp[k];
                const u64 sp2  = splat2(sp[k]);
                const u64 dbu2 = splat2(sp[k] * uu[k]);

                const float4* Bt = reinterpret_cast<const float4*>(&Bsm[tt][0]);
                F4P b0, b1, b2, b3;
                b0.v = Bt[0]; b1.v = Bt[1]; b2.v = Bt[2]; b3.v = Bt[3];
                const u64 B2[8] = {b0.p[0], b0.p[1], b1.p[0], b1.p[1],
                                   b2.p[0], b2.p[1], b3.p[0], b3.p[1]};
                #pragma unroll
                for (int p = 0; p < 8; p++) {
                    const u64 a2 = ex2_pair(mul2(sp2, A2p[p]));
                    h2[p] = fma2(a2, h2[p], mul2(dbu2, B2[p]));
                }
            }
        }
    }

    float* __restrict__ hp = g_hloc + ((size_t)row * CHUNKS + chunk) * NST;
    #pragma unroll
    for (int q = 0; q < 4; q++) {
        F4P o; o.p[0] = h2[q*2+0]; o.p[1] = h2[q*2+1];
        *reinterpret_cast<float4*>(hp + q * 4) = o.v;
    }
    g_sumsp[row * CHUNKS + chunk] = ssum;
}

// ------------------------------------------------------------------ phase 2
// One thread per (row, n): sequential combine over CHUNKS.
__global__ void __launch_bounds__(256) phase2_kernel(const float* __restrict__ A) {
    const int idx = blockIdx.x * blockDim.x + threadIdx.x;   // 0..ROWS*NST-1
    const int row = idx >> 4;
    const int n   = idx & (NST - 1);
    const int d   = row & (DDIM - 1);
    const float A2 = A[d * NST + n] * LOG2E;

    float H = 0.0f;
    #pragma unroll 8
    for (int c = 0; c < CHUNKS; c++) {
        g_carry[((size_t)row * CHUNKS + c) * NST + n] = H;
        float P = ex2f(A2 * g_sumsp[row * CHUNKS + c]);
        H = fmaf(P, H, g_hloc[((size_t)row * CHUNKS + c) * NST + n]);
    }
}

// ------------------------------------------------------------------ phase 3
// Thread = (row, chunk); h from carry; sp/u via coalesced direct LDG from the
// transposed scratch; z double-buffered through smem with cp.async prefetch;
// y written in-place into the consumed z buffer then swept out coalesced.
__global__ void __launch_bounds__(128) phase3_kernel(const float* __restrict__ A,
                                                     const float* __restrict__ B,
                                                     const float* __restrict__ C,
                                                     const float* __restrict__ Dv,
                                                     const float* __restrict__ z,
                                                     float* __restrict__ y) {
    __shared__ __align__(16) float Bsm[CLEN][BPITCH];
    __shared__ __align__(16) float Csm[CLEN][BPITCH];
    __shared__ __align__(16) float Zt[2][128][TPITCH];   // z in / y out

    const int tid     = threadIdx.x;
    const int rowbase = blockIdx.x * 128;
    const int row     = rowbase + tid;
    const int chunk   = blockIdx.y;
    const int b       = row >> 10;
    const int d       = row & (DDIM - 1);
    const int t0      = chunk * CLEN;

    // Kick off z prefetch for subtile 0 immediately (overlaps B/C staging).
    #pragma unroll
    for (int s = 0; s < 8; s++) {
        const int f = s * 128 + tid;
        const int r = f >> 3;
        const int c = (f & 7) << 2;
        unsigned sm = (unsigned)__cvta_generic_to_shared(&Zt[0][r][c]);
        const float* g = z + (size_t)(rowbase + r) * LEN + t0 + c;
        asm volatile("cp.async.ca.shared.global [%0], [%1], 16;" :: "r"(sm), "l"(g));
    }
    asm volatile("cp.async.commit_group;");

    const float* __restrict__ Bb = B + (size_t)b * NST * LEN + t0;
    const float* __restrict__ Cb = C + (size_t)b * NST * LEN + t0;
    #pragma unroll
    for (int i = tid; i < NST * (CLEN / 4); i += 128) {
        const int nn = i >> 4;
        const int t4 = (i & 15) << 2;
        float4 v = *reinterpret_cast<const float4*>(Bb + nn * LEN + t4);
        Bsm[t4 + 0][nn] = v.x; Bsm[t4 + 1][nn] = v.y;
        Bsm[t4 + 2][nn] = v.z; Bsm[t4 + 3][nn] = v.w;
        float4 w = *reinterpret_cast<const float4*>(Cb + nn * LEN + t4);
        Csm[t4 + 0][nn] = w.x; Csm[t4 + 1][nn] = w.y;
        Csm[t4 + 2][nn] = w.z; Csm[t4 + 3][nn] = w.w;
    }

    // Prefetch z for subtile 1 into buffer 1.
    #pragma unroll
    for (int s = 0; s < 8; s++) {
        const int f = s * 128 + tid;
        const int r = f >> 3;
        const int c = (f & 7) << 2;
        unsigned sm = (unsigned)__cvta_generic_to_shared(&Zt[1][r][c]);
        const float* g = z + (size_t)(rowbase + r) * LEN + t0 + SUBT + c;
        asm volatile("cp.async.ca.shared.global [%0], [%1], 16;" :: "r"(sm), "l"(g));
    }
    asm volatile("cp.async.commit_group;");

    u64 A2p[8];
    {
        const u64 l2 = splat2(LOG2E);
        const float4* Ap = reinterpret_cast<const float4*>(A + d * NST);
        #pragma unroll
        for (int q = 0; q < 4; q++) {
            F4P a; a.v = Ap[q];
            A2p[q*2+0] = mul2(a.p[0], l2);
            A2p[q*2+1] = mul2(a.p[1], l2);
        }
    }
    const float Dd = Dv[d];

    u64 h2[8];
    {
        const float4* cp = reinterpret_cast<const float4*>(
            g_carry + ((size_t)row * CHUNKS + chunk) * NST);
        #pragma unroll
        for (int q = 0; q < 4; q++) {
            F4P c4; c4.v = cp[q];
            h2[q*2+0] = c4.p[0];
            h2[q*2+1] = c4.p[1];
        }
    }

    #pragma unroll
    for (int sub = 0; sub < CLEN / SUBT; sub++) {     // exactly 2 iterations
        const int tb  = t0 + sub * SUBT;
        const int buf = sub;

        // Wait for this subtile's z (leave the other group in flight on sub 0).
        if (sub == 0) {
            asm volatile("cp.async.wait_group 1;");
        } else {
            asm volatile("cp.async.wait_group 0;");
        }
        __syncthreads();   // all threads' cp.async results + prev writeout done

        const float* __restrict__ sptp = g_spt + (size_t)tb * ROWS + row;
        const float* __restrict__ utp  = g_ut  + (size_t)tb * ROWS + row;

        #pragma unroll 1
        for (int tq = 0; tq < SUBT; tq += 4) {
            float4 z4 = *reinterpret_cast<const float4*>(&Zt[buf][tid][tq]);
            float zz[4] = {z4.x, z4.y, z4.z, z4.w};
            float sp[4], uu[4];
            #pragma unroll
            for (int k = 0; k < 4; k++) {
                sp[k] = sptp[(size_t)(tq + k) * ROWS];
                uu[k] = utp [(size_t)(tq + k) * ROWS];
            }
            float r4[4];

            #pragma unroll
            for (int k = 0; k < 4; k++) {
                const int tt    = sub * SUBT + tq + k;
                const float spv = sp[k];
                const float uv  = uu[k];
                const u64 sp2   = splat2(spv);
                const u64 dbu2  = splat2(spv * uv);

                const float4* Bt = reinterpret_cast<const float4*>(&Bsm[tt][0]);
                const float4* Ct = reinterpret_cast<const float4*>(&Csm[tt][0]);
                F4P b0, b1, b2, b3, c0, c1, c2, c3;
                b0.v = Bt[0]; b1.v = Bt[1]; b2.v = Bt[2]; b3.v = Bt[3];
                c0.v = Ct[0]; c1.v = Ct[1]; c2.v = Ct[2]; c3.v = Ct[3];
                const u64 B2[8] = {b0.p[0], b0.p[1], b1.p[0], b1.p[1],
                                   b2.p[0], b2.p[1], b3.p[0], b3.p[1]};
                const u64 C2[8] = {c0.p[0], c0.p[1], c1.p[0], c1.p[1],
                                   c2.p[0], c2.p[1], c3.p[0], c3.p[1]};

                u64 accA = 0ull, accB = 0ull;
                #pragma unroll
                for (int p = 0; p < 8; p += 2) {
                    const u64 a2_0 = ex2_pair(mul2(sp2, A2p[p]));
                    h2[p] = fma2(a2_0, h2[p], mul2(dbu2, B2[p]));
                    accA = fma2(C2[p], h2[p], accA);
                    const u64 a2_1 = ex2_pair(mul2(sp2, A2p[p+1]));
                    h2[p+1] = fma2(a2_1, h2[p+1], mul2(dbu2, B2[p+1]));
                    accB = fma2(C2[p+1], h2[p+1], accB);
                }
                U2F acc; acc.u = add2(accA, accB);
                const float sres = (acc.f[0] + acc.f[1]) + uv * Dd;
                r4[k] = sres * silu_t(zz[k]);
            }

            // overwrite own row's z slots with y (same owner thread, no hazard)
            *reinterpret_cast<float4*>(&Zt[buf][tid][tq]) =
                make_float4(r4[0], r4[1], r4[2], r4[3]);
        }

        __syncthreads();   // y tile complete
        #pragma unroll
        for (int s = 0; s < 8; s++) {
            const int f = s * 128 + tid;
            const int r = f >> 3;
            const int c = (f & 7) << 2;
            *reinterpret_cast<float4*>(y + (size_t)(rowbase + r) * LEN + tb + c) =
                *reinterpret_cast<const float4*>(&Zt[buf][r][c]);
        }
    }
}

extern "C" void kernel_launch(void* const* d_in, const int* in_sizes, int n_in,
                              void* d_out, int out_size) {
    // metadata order: u, delta, A, B, C, D, z, delta_softplus
    const float* u     = (const float*)d_in[0];
    const float* delta = (const float*)d_in[1];
    const float* A     = (const float*)d_in[2];
    const float* B     = (const float*)d_in[3];
    const float* C     = (const float*)d_in[4];
    const float* D     = (const float*)d_in[5];
    const float* z     = (const float*)d_in[6];
    float* y = (float*)d_out;

    dim3 grid1(ROWS / 128, CHUNKS);
    phase1_kernel<<<grid1, 128>>>(u, delta, A, B);
    phase2_kernel<<<(ROWS * NST) / 256, 256>>>(A);
    phase3_kernel<<<grid1, 128>>>(A, B, C, D, z, y);
}

// round 14
// speedup vs baseline: 1.3225x; 1.0582x over previous
#include <cuda_runtime.h>
#include <math.h>

// Problem shape (fixed by reference setup_inputs)
#define BATCH  2
#define DDIM   1024
#define NST    16
#define LEN    2048
#define ROWS   (BATCH * DDIM)     // 2048
#define CHUNKS 32
#define CLEN   (LEN / CHUNKS)     // 64
#define SUBT   32                 // staging subtile (timesteps) = 128B rows
#define BPITCH 20                 // B/C smem pitch in floats (80B, 16B-aligned)
#define TPITCH 36                 // row-tile pitch in floats (144B, 16B-aligned)
#define LOG2E    1.4426950408889634f
#define RCP_LOG2 0.6931471805599453f

// Scratch (no cudaMalloc allowed)
__device__ float g_spt  [LEN * ROWS];           // softplus(delta), transposed [t][row]
__device__ float g_hloc [ROWS * CHUNKS * NST];  // per-chunk local final state
__device__ float g_sumsp[ROWS * CHUNKS];        // per-chunk sum of softplus
__device__ float g_carry[ROWS * CHUNKS * NST];  // carry-in state per chunk

typedef unsigned long long u64;

union F4P { float4 v; u64 p[2]; };
union U2F { u64 u; float f[2]; };

__device__ __forceinline__ u64 mul2(u64 a, u64 b) {
    u64 d;
    asm("mul.rn.f32x2 %0, %1, %2;" : "=l"(d) : "l"(a), "l"(b));
    return d;
}
__device__ __forceinline__ u64 fma2(u64 a, u64 b, u64 c) {
    u64 d;
    asm("fma.rn.f32x2 %0, %1, %2, %3;" : "=l"(d) : "l"(a), "l"(b), "l"(c));
    return d;
}
__device__ __forceinline__ u64 add2(u64 a, u64 b) {
    u64 d;
    asm("add.rn.f32x2 %0, %1, %2;" : "=l"(d) : "l"(a), "l"(b));
    return d;
}
__device__ __forceinline__ u64 splat2(float x) {
    U2F r; r.f[0] = x; r.f[1] = x; return r.u;
}

__device__ __forceinline__ float ex2f(float x) {
    float y;
    asm("ex2.approx.ftz.f32 %0, %1;" : "=f"(y) : "f"(x));
    return y;
}
__device__ __forceinline__ float lg2f(float x) {
    float y;
    asm("lg2.approx.ftz.f32 %0, %1;" : "=f"(y) : "f"(x));
    return y;
}
__device__ __forceinline__ float softplus_f(float x) {
    if (x > 20.0f) return x;
    return lg2f(1.0f + ex2f(x * LOG2E)) * RCP_LOG2;
}
// silu via tanh.approx: 1 MUFU instead of ex2 + rcp.
// sigmoid(z) = 0.5*(1 + tanh(z/2)); abs err ~1e-4 -> global rel_err ~2.6e-6 (R13-measured).
__device__ __forceinline__ float silu_t(float z) {
    float t;
    asm("tanh.approx.f32 %0, %1;" : "=f"(t) : "f"(z * 0.5f));
    return z * fmaf(t, 0.5f, 0.5f);
}

// exp2 of both halves via MUFU (XU pipe) — proven fastest variant (round 8).
__device__ __forceinline__ u64 ex2_pair(u64 x2) {
    U2F in; in.u = x2;
    U2F out;
    out.f[0] = ex2f(in.f[0]);
    out.f[1] = ex2f(in.f[1]);
    return out.u;
}

// ------------------------------------------------------------------ phase 1
// Thread = (row, chunk), 16 states in 8 packed f32x2 registers.
// Block = 128 rows, one chunk. Grid = (ROWS/128, CHUNKS) = (16, 32).
__global__ void __launch_bounds__(128) phase1_kernel(const float* __restrict__ u,
                                                     const float* __restrict__ delta,
                                                     const float* __restrict__ A,
                                                     const float* __restrict__ B) {
    __shared__ __align__(16) float Bsm[CLEN][BPITCH];
    __shared__ __align__(16) float Dt[128][TPITCH];
    __shared__ __align__(16) float Ut[128][TPITCH];

    const int tid     = threadIdx.x;
    const int rowbase = blockIdx.x * 128;
    const int row     = rowbase + tid;
    const int chunk   = blockIdx.y;
    const int b       = row >> 10;         // DDIM = 1024
    const int d       = row & (DDIM - 1);
    const int t0      = chunk * CLEN;

    // Stage B tile [t][n]
    const float* __restrict__ Bb = B + (size_t)b * NST * LEN + t0;
    #pragma unroll
    for (int i = tid; i < NST * (CLEN / 4); i += 128) {
        const int nn = i >> 4;             // CLEN/4 = 16 slots per state
        const int t4 = (i & 15) << 2;
        float4 v = *reinterpret_cast<const float4*>(Bb + nn * LEN + t4);
        Bsm[t4 + 0][nn] = v.x; Bsm[t4 + 1][nn] = v.y;
        Bsm[t4 + 2][nn] = v.z; Bsm[t4 + 3][nn] = v.w;
    }

    u64 A2p[8];
    {
        const u64 l2 = splat2(LOG2E);
        const float4* Ap = reinterpret_cast<const float4*>(A + d * NST);
        #pragma unroll
        for (int q = 0; q < 4; q++) {
            F4P a; a.v = Ap[q];
            A2p[q*2+0] = mul2(a.p[0], l2);
            A2p[q*2+1] = mul2(a.p[1], l2);
        }
    }

    u64 h2[8];
    #pragma unroll
    for (int p = 0; p < 8; p++) h2[p] = 0ull;
    float ssum = 0.0f;

    #pragma unroll 1
    for (int sub = 0; sub < CLEN / SUBT; sub++) {
        const int tb = t0 + sub * SUBT;
        __syncthreads();   // previous tile fully consumed / B staged
        #pragma unroll
        for (int s = 0; s < 8; s++) {
            const int f = s * 128 + tid;
            const int r = f >> 3;
            const int c = (f & 7) << 2;
            const size_t gofs = (size_t)(rowbase + r) * LEN + tb + c;
            *reinterpret_cast<float4*>(&Dt[r][c]) =
                *reinterpret_cast<const float4*>(delta + gofs);
            *reinterpret_cast<float4*>(&Ut[r][c]) =
                *reinterpret_cast<const float4*>(u + gofs);
        }
        __syncthreads();

        float* __restrict__ sptp = g_spt + (size_t)tb * ROWS + row;

        #pragma unroll 1
        for (int tq = 0; tq < SUBT; tq += 4) {
            float4 d4 = *reinterpret_cast<const float4*>(&Dt[tid][tq]);
            float4 u4 = *reinterpret_cast<const float4*>(&Ut[tid][tq]);
            float sp[4] = {softplus_f(d4.x), softplus_f(d4.y),
                           softplus_f(d4.z), softplus_f(d4.w)};
            float uu[4] = {u4.x, u4.y, u4.z, u4.w};

            #pragma unroll
            for (int k = 0; k < 4; k++) {
                const int tt = sub * SUBT + tq + k;   // index into Bsm
                sptp[(size_t)(tq + k) * ROWS] = sp[k];
                ssum += sp[k];
                const u64 sp2  = splat2(sp[k]);
                const u64 dbu2 = splat2(sp[k] * uu[k]);

                const float4* Bt = reinterpret_cast<const float4*>(&Bsm[tt][0]);
                F4P b0, b1, b2, b3;
                b0.v = Bt[0]; b1.v = Bt[1]; b2.v = Bt[2]; b3.v = Bt[3];
                const u64 B2[8] = {b0.p[0], b0.p[1], b1.p[0], b1.p[1],
                                   b2.p[0], b2.p[1], b3.p[0], b3.p[1]};
                #pragma unroll
                for (int p = 0; p < 8; p++) {
                    const u64 a2 = ex2_pair(mul2(sp2, A2p[p]));
                    h2[p] = fma2(a2, h2[p], mul2(dbu2, B2[p]));
                }
            }
        }
    }

    float* __restrict__ hp = g_hloc + ((size_t)row * CHUNKS + chunk) * NST;
    #pragma unroll
    for (int q = 0; q < 4; q++) {
        F4P o; o.p[0] = h2[q*2+0]; o.p[1] = h2[q*2+1];
        *reinterpret_cast<float4*>(hp + q * 4) = o.v;
    }
    g_sumsp[row * CHUNKS + chunk] = ssum;
}

// ------------------------------------------------------------------ phase 2
// One thread per (row, n): sequential combine over CHUNKS.
__global__ void __launch_bounds__(256) phase2_kernel(const float* __restrict__ A) {
    const int idx = blockIdx.x * blockDim.x + threadIdx.x;   // 0..ROWS*NST-1
    const int row = idx >> 4;
    const int n   = idx & (NST - 1);
    const int d   = row & (DDIM - 1);
    const float A2 = A[d * NST + n] * LOG2E;

    float H = 0.0f;
    #pragma unroll
    for (int c = 0; c < CHUNKS; c++) {
        g_carry[((size_t)row * CHUNKS + c) * NST + n] = H;
        float P = ex2f(A2 * g_sumsp[row * CHUNKS + c]);
        H = fmaf(P, H, g_hloc[((size_t)row * CHUNKS + c) * NST + n]);
    }
}

// ------------------------------------------------------------------ phase 3
// Same layout as phase 1; h starts from carry; adds C-reduction + output.
__global__ void __launch_bounds__(128) phase3_kernel(const float* __restrict__ u,
                                                     const float* __restrict__ A,
                                                     const float* __restrict__ B,
                                                     const float* __restrict__ C,
                                                     const float* __restrict__ Dv,
                                                     const float* __restrict__ z,
                                                     float* __restrict__ y) {
    __shared__ __align__(16) float Bsm[CLEN][BPITCH];
    __shared__ __align__(16) float Csm[CLEN][BPITCH];
    __shared__ __align__(16) float Ut[128][TPITCH];   // holds u, then reused for y
    __shared__ __align__(16) float Zt[128][TPITCH];

    const int tid     = threadIdx.x;
    const int rowbase = blockIdx.x * 128;
    const int row     = rowbase + tid;
    const int chunk   = blockIdx.y;
    const int b       = row >> 10;
    const int d       = row & (DDIM - 1);
    const int t0      = chunk * CLEN;

    const float* __restrict__ Bb = B + (size_t)b * NST * LEN + t0;
    const float* __restrict__ Cb = C + (size_t)b * NST * LEN + t0;
    #pragma unroll
    for (int i = tid; i < NST * (CLEN / 4); i += 128) {
        const int nn = i >> 4;
        const int t4 = (i & 15) << 2;
        float4 v = *reinterpret_cast<const float4*>(Bb + nn * LEN + t4);
        Bsm[t4 + 0][nn] = v.x; Bsm[t4 + 1][nn] = v.y;
        Bsm[t4 + 2][nn] = v.z; Bsm[t4 + 3][nn] = v.w;
        float4 w = *reinterpret_cast<const float4*>(Cb + nn * LEN + t4);
        Csm[t4 + 0][nn] = w.x; Csm[t4 + 1][nn] = w.y;
        Csm[t4 + 2][nn] = w.z; Csm[t4 + 3][nn] = w.w;
    }

    u64 A2p[8];
    {
        const u64 l2 = splat2(LOG2E);
        const float4* Ap = reinterpret_cast<const float4*>(A + d * NST);
        #pragma unroll
        for (int q = 0; q < 4; q++) {
            F4P a; a.v = Ap[q];
            A2p[q*2+0] = mul2(a.p[0], l2);
            A2p[q*2+1] = mul2(a.p[1], l2);
        }
    }
    const float Dd = Dv[d];

    u64 h2[8];
    {
        const float4* cp = reinterpret_cast<const float4*>(
            g_carry + ((size_t)row * CHUNKS + chunk) * NST);
        #pragma unroll
        for (int q = 0; q < 4; q++) {
            F4P c4; c4.v = cp[q];
            h2[q*2+0] = c4.p[0];
            h2[q*2+1] = c4.p[1];
        }
    }

    #pragma unroll 1
    for (int sub = 0; sub < CLEN / SUBT; sub++) {
        const int tb = t0 + sub * SUBT;
        __syncthreads();   // previous writeout complete / B,C staged
        #pragma unroll
        for (int s = 0; s < 8; s++) {
            const int f = s * 128 + tid;
            const int r = f >> 3;
            const int c = (f & 7) << 2;
            const size_t gofs = (size_t)(rowbase + r) * LEN + tb + c;
            *reinterpret_cast<float4*>(&Ut[r][c]) =
                *reinterpret_cast<const float4*>(u + gofs);
            *reinterpret_cast<float4*>(&Zt[r][c]) =
                *reinterpret_cast<const float4*>(z + gofs);
        }
        __syncthreads();

        const float* __restrict__ sptp = g_spt + (size_t)tb * ROWS + row;

        #pragma unroll 1
        for (int tq = 0; tq < SUBT; tq += 4) {
            float4 u4 = *reinterpret_cast<const float4*>(&Ut[tid][tq]);
            float4 z4 = *reinterpret_cast<const float4*>(&Zt[tid][tq]);
            float uu[4] = {u4.x, u4.y, u4.z, u4.w};
            float zz[4] = {z4.x, z4.y, z4.z, z4.w};
            float r4[4];

            #pragma unroll
            for (int k = 0; k < 4; k++) {
                const int tt    = sub * SUBT + tq + k;
                const float spv = sptp[(size_t)(tq + k) * ROWS];
                const float uv  = uu[k];
                const u64 sp2   = splat2(spv);
                const u64 dbu2  = splat2(spv * uv);

                const float4* Bt = reinterpret_cast<const float4*>(&Bsm[tt][0]);
                const float4* Ct = reinterpret_cast<const float4*>(&Csm[tt][0]);
                F4P b0, b1, b2, b3, c0, c1, c2, c3;
                b0.v = Bt[0]; b1.v = Bt[1]; b2.v = Bt[2]; b3.v = Bt[3];
                c0.v = Ct[0]; c1.v = Ct[1]; c2.v = Ct[2]; c3.v = Ct[3];
                const u64 B2[8] = {b0.p[0], b0.p[1], b1.p[0], b1.p[1],
                                   b2.p[0], b2.p[1], b3.p[0], b3.p[1]};
                const u64 C2[8] = {c0.p[0], c0.p[1], c1.p[0], c1.p[1],
                                   c2.p[0], c2.p[1], c3.p[0], c3.p[1]};

                u64 accA = 0ull, accB = 0ull;
                #pragma unroll
                for (int p = 0; p < 8; p += 2) {
                    const u64 a2_0 = ex2_pair(mul2(sp2, A2p[p]));
                    h2[p] = fma2(a2_0, h2[p], mul2(dbu2, B2[p]));
                    accA = fma2(C2[p], h2[p], accA);
                    const u64 a2_1 = ex2_pair(mul2(sp2, A2p[p+1]));
                    h2[p+1] = fma2(a2_1, h2[p+1], mul2(dbu2, B2[p+1]));
                    accB = fma2(C2[p+1], h2[p+1], accB);
                }
                U2F acc; acc.u = add2(accA, accB);
                const float s = (acc.f[0] + acc.f[1]) + uv * Dd;
                r4[k] = s * silu_t(zz[k]);
            }

            // Reuse the u tile as the y tile (u[tq..tq+3] already consumed)
            *reinterpret_cast<float4*>(&Ut[tid][tq]) =
                make_float4(r4[0], r4[1], r4[2], r4[3]);
        }

        __syncthreads();   // y tile complete
        #pragma unroll
        for (int s = 0; s < 8; s++) {
            const int f = s * 128 + tid;
            const int r = f >> 3;
            const int c = (f & 7) << 2;
            *reinterpret_cast<float4*>(y + (size_t)(rowbase + r) * LEN + tb + c) =
                *reinterpret_cast<const float4*>(&Ut[r][c]);
        }
    }
}

extern "C" void kernel_launch(void* const* d_in, const int* in_sizes, int n_in,
                              void* d_out, int out_size) {
    // metadata order: u, delta, A, B, C, D, z, delta_softplus
    const float* u     = (const float*)d_in[0];
    const float* delta = (const float*)d_in[1];
    const float* A     = (const float*)d_in[2];
    const float* B     = (const float*)d_in[3];
    const float* C     = (const float*)d_in[4];
    const float* D     = (const float*)d_in[5];
    const float* z     = (const float*)d_in[6];
    float* y = (float*)d_out;

    dim3 grid1(ROWS / 128, CHUNKS);
    phase1_kernel<<<grid1, 128>>>(u, delta, A, B);
    phase2_kernel<<<(ROWS * NST) / 256, 256>>>(A);
    phase3_kernel<<<grid1, 128>>>(u, A, B, C, D, z, y);
}